// round 7
// baseline (speedup 1.0000x reference)
#include <cuda_runtime.h>
#include <cuda_bf16.h>
#include <cstdint>

#define MM 32768
#define KK 1024
#define NN 1024
#define NBR 5

// ------------------- static device scratch ---------------------------------
__device__ __nv_bfloat16 g_xhi[(size_t)MM * KK];         // bf16 hi of x
__device__ __nv_bfloat16 g_whi[(size_t)NN * KK];         // bf16 hi of W
__device__ char g_xq[(size_t)MM * 2048];                 // [m][ q_xlo(1024) | q_xhi(1024) ]
__device__ char g_wq[(size_t)NN * 2048];                 // [n][ q_whi(1024) | q_wlo(1024) ]
__device__ float g_sx[MM];                               // per-row x scale
__device__ float g_sw[NN];                               // per-row W scale * 2^-9
__device__ __nv_bfloat16 g_abf[80 * KK];                 // A (shared+tasks) bf16
__device__ __nv_bfloat16 g_bc[(size_t)NBR * NN * 16];    // scaled B, bf16
__device__ __nv_bfloat16 g_xa[(size_t)MM * 80];          // XA bf16

// ------------------- helpers -----------------------------------------------
__device__ __forceinline__ uint32_t s2u(const void* p) {
    uint32_t a;
    asm("{ .reg .u64 t; cvta.to.shared.u64 t, %1; cvt.u32.u64 %0, t; }" : "=r"(a) : "l"(p));
    return a;
}
#define CPA16(d, s) asm volatile("cp.async.cg.shared.global [%0], [%1], 16;" :: "r"(d), "l"(s))
#define CPCOMMIT()  asm volatile("cp.async.commit_group;")
#define CPWAIT(n)   asm volatile("cp.async.wait_group %0;" :: "n"(n))

__device__ __forceinline__ void ldsm4(uint32_t* r, uint32_t a) {
    asm volatile("ldmatrix.sync.aligned.m8n8.x4.shared.b16 {%0,%1,%2,%3}, [%4];"
                 : "=r"(r[0]), "=r"(r[1]), "=r"(r[2]), "=r"(r[3]) : "r"(a));
}
__device__ __forceinline__ void ldsm2(uint32_t* r, uint32_t a) {
    asm volatile("ldmatrix.sync.aligned.m8n8.x2.shared.b16 {%0,%1}, [%2];"
                 : "=r"(r[0]), "=r"(r[1]) : "r"(a));
}
__device__ __forceinline__ void mma16816(float* c, const uint32_t* a, uint32_t b0, uint32_t b1) {
    asm volatile("mma.sync.aligned.m16n8k16.row.col.f32.bf16.bf16.f32 "
                 "{%0,%1,%2,%3},{%4,%5,%6,%7},{%8,%9},{%0,%1,%2,%3};"
                 : "+f"(c[0]), "+f"(c[1]), "+f"(c[2]), "+f"(c[3])
                 : "r"(a[0]), "r"(a[1]), "r"(a[2]), "r"(a[3]), "r"(b0), "r"(b1));
}
__device__ __forceinline__ void imma16832(int* c, const uint32_t* a, uint32_t b0, uint32_t b1) {
    asm volatile("mma.sync.aligned.m16n8k32.row.col.s32.s8.s8.s32 "
                 "{%0,%1,%2,%3},{%4,%5,%6,%7},{%8,%9},{%0,%1,%2,%3};"
                 : "+r"(c[0]), "+r"(c[1]), "+r"(c[2]), "+r"(c[3])
                 : "r"(a[0]), "r"(a[1]), "r"(a[2]), "r"(a[3]), "r"(b0), "r"(b1));
}
__device__ __forceinline__ void split2(float v, __nv_bfloat16& h, __nv_bfloat16& l) {
    h = __float2bfloat16(v);
    l = __float2bfloat16(v - __bfloat162float(h));
}
__device__ __forceinline__ int q8(float v) {
    int q = __float2int_rn(v);
    return max(-127, min(127, q));
}

// ------------------- quantization prep kernels -----------------------------
// One warp per row: compute row max, write bf16-hi + int8 [lo | hi] + scale.
__global__ void __launch_bounds__(256) quant_x_k(const float* __restrict__ x) {
    const int r = blockIdx.x * 8 + (threadIdx.x >> 5);
    const int l = threadIdx.x & 31;
    const float4* row = (const float4*)(x + (size_t)r * KK);
    float4 v[8];
    float mx = 0.f;
#pragma unroll
    for (int it = 0; it < 8; ++it) {
        v[it] = row[it * 32 + l];
        mx = fmaxf(mx, fmaxf(fmaxf(fabsf(v[it].x), fabsf(v[it].y)),
                             fmaxf(fabsf(v[it].z), fabsf(v[it].w))));
    }
#pragma unroll
    for (int o = 16; o; o >>= 1) mx = fmaxf(mx, __shfl_xor_sync(~0u, mx, o));
    float sx = (mx == 0.f) ? 1.f : mx * (1.02f / 127.f);
    float inv = 1.f / sx, inv9 = inv * 512.f;
#pragma unroll
    for (int it = 0; it < 8; ++it) {
        int k = it * 128 + l * 4;
        float f[4] = {v[it].x, v[it].y, v[it].z, v[it].w};
        uint32_t hp[2], qh = 0, ql = 0;
        __nv_bfloat162 h2[2];
#pragma unroll
        for (int j = 0; j < 4; ++j) {
            __nv_bfloat16 h = __float2bfloat16(f[j]);
            float hf = __bfloat162float(h);
            ((__nv_bfloat16*)h2)[j] = h;
            qh |= (uint32_t)(q8(hf * inv) & 0xff) << (j * 8);
            ql |= (uint32_t)(q8((f[j] - hf) * inv9) & 0xff) << (j * 8);
        }
        hp[0] = ((uint32_t*)h2)[0]; hp[1] = ((uint32_t*)h2)[1];
        *(uint2*)(g_xhi + (size_t)r * KK + k) = make_uint2(hp[0], hp[1]);
        *(uint32_t*)(g_xq + (size_t)r * 2048 + k) = ql;
        *(uint32_t*)(g_xq + (size_t)r * 2048 + 1024 + k) = qh;
    }
    if (l == 0) g_sx[r] = sx;
}

__global__ void __launch_bounds__(256) quant_w_k(const float* __restrict__ w) {
    const int r = blockIdx.x * 8 + (threadIdx.x >> 5);
    const int l = threadIdx.x & 31;
    const float4* row = (const float4*)(w + (size_t)r * KK);
    float4 v[8];
    float mx = 0.f;
#pragma unroll
    for (int it = 0; it < 8; ++it) {
        v[it] = row[it * 32 + l];
        mx = fmaxf(mx, fmaxf(fmaxf(fabsf(v[it].x), fabsf(v[it].y)),
                             fmaxf(fabsf(v[it].z), fabsf(v[it].w))));
    }
#pragma unroll
    for (int o = 16; o; o >>= 1) mx = fmaxf(mx, __shfl_xor_sync(~0u, mx, o));
    float sw = (mx == 0.f) ? 1.f : mx * (1.02f / 127.f);
    float inv = 1.f / sw, inv9 = inv * 512.f;
#pragma unroll
    for (int it = 0; it < 8; ++it) {
        int k = it * 128 + l * 4;
        float f[4] = {v[it].x, v[it].y, v[it].z, v[it].w};
        uint32_t hp[2], qh = 0, ql = 0;
        __nv_bfloat162 h2[2];
#pragma unroll
        for (int j = 0; j < 4; ++j) {
            __nv_bfloat16 h = __float2bfloat16(f[j]);
            float hf = __bfloat162float(h);
            ((__nv_bfloat16*)h2)[j] = h;
            qh |= (uint32_t)(q8(hf * inv) & 0xff) << (j * 8);
            ql |= (uint32_t)(q8((f[j] - hf) * inv9) & 0xff) << (j * 8);
        }
        hp[0] = ((uint32_t*)h2)[0]; hp[1] = ((uint32_t*)h2)[1];
        *(uint2*)(g_whi + (size_t)r * KK + k) = make_uint2(hp[0], hp[1]);
        *(uint32_t*)(g_wq + (size_t)r * 2048 + k) = qh;           // q_whi first
        *(uint32_t*)(g_wq + (size_t)r * 2048 + 1024 + k) = ql;    // q_wlo second
    }
    if (l == 0) g_sw[r] = sw * (1.f / 512.f);
}

__global__ void __launch_bounds__(256) conv_a_k(const float* __restrict__ A_sh,
                                                const float* __restrict__ A_tasks) {
    size_t i = ((size_t)blockIdx.x * 256 + threadIdx.x) * 4;   // < 81920
    const float* src = (i < 16384) ? (A_sh + i) : (A_tasks + (i - 16384));
    float4 v = *(const float4*)src;
    __nv_bfloat162 a{__float2bfloat16(v.x), __float2bfloat16(v.y)};
    __nv_bfloat162 b{__float2bfloat16(v.z), __float2bfloat16(v.w)};
    ((__nv_bfloat162*)(g_abf + i))[0] = a; ((__nv_bfloat162*)(g_abf + i))[1] = b;
}
__global__ void __launch_bounds__(256) prep_bc_k(const float* __restrict__ B_sh,
                                                 const float* __restrict__ B_tasks,
                                                 const float* __restrict__ ts) {
    int id = blockIdx.x * 256 + threadIdx.x;   // < 5120
    int br = id >> 10, n = id & 1023;
    const float* row = (br == 0) ? (B_sh + (size_t)n * 16)
                                 : (B_tasks + ((size_t)(br - 1) * NN + n) * 16);
    float s = (br == 0) ? 1.0f : ts[br - 1];
    __nv_bfloat16* dst = g_bc + ((size_t)br * NN + n) * 16;
#pragma unroll
    for (int r = 0; r < 16; ++r) dst[r] = __float2bfloat16(s * row[r]);
}

// ------------------- XA kernel (HMMA, single bf16) --------------------------
#define XA_STG 26624

__device__ __forceinline__ void xa_load(int c, uint32_t sb, int m0, int tid) {
    int k0 = c << 6;
#pragma unroll
    for (int i = 0; i < 7; ++i) {
        int id = tid + (i << 8);
        if (id < 1024) {
            int row = id >> 3, c16 = id & 7;
            CPA16(sb + row * 128 + ((c16 ^ (row & 7)) << 4),
                  (const char*)(g_xhi + (size_t)(m0 + row) * KK + k0) + c16 * 16);
        } else if (id < 1664) {
            int id2 = id - 1024;
            int row = id2 >> 3, c16 = id2 & 7;
            CPA16(sb + 16384 + row * 128 + ((c16 ^ (row & 7)) << 4),
                  (const char*)(g_abf + (size_t)row * KK + k0) + c16 * 16);
        }
    }
}

__global__ void __launch_bounds__(256, 1) xa_kernel() {
    extern __shared__ char sm[];
    const uint32_t base = s2u(sm);
    const int tid = threadIdx.x, wid = tid >> 5, l = tid & 31;
    const int m0 = blockIdx.x * 128;
    const int wm = wid & 3, wn = wid >> 2;

    float acc[2][5][4];
#pragma unroll
    for (int i = 0; i < 2; ++i)
#pragma unroll
        for (int j = 0; j < 5; ++j)
#pragma unroll
            for (int k = 0; k < 4; ++k) acc[i][j][k] = 0.f;

    xa_load(0, base, m0, tid); CPCOMMIT();
    xa_load(1, base + XA_STG, m0, tid); CPCOMMIT();

    const uint32_t arow  = (uint32_t)((wm * 32 + (l & 15)) * 128);
    const uint32_t brow  = (uint32_t)((wn * 40 + (l & 15)) * 128) + 16384;
    const uint32_t brow2 = (uint32_t)((wn * 40 + 32 + (l & 7)) * 128) + 16384;
    const uint32_t ax = (uint32_t)(l & 7);
    const uint32_t hi16 = (uint32_t)(l >> 4);
    const uint32_t sel2 = (uint32_t)((l >> 3) & 1);

    for (int c = 0; c < 16; ++c) {
        uint32_t sb = base + (c % 3) * XA_STG;
        if (c == 15) { CPWAIT(0); } else { CPWAIT(1); }
        __syncthreads();
        if (c + 2 < 16) { xa_load(c + 2, base + ((c + 2) % 3) * XA_STG, m0, tid); CPCOMMIT(); }
#pragma unroll
        for (int ks = 0; ks < 4; ++ks) {
            uint32_t kc = (uint32_t)(ks * 2);
            uint32_t a[2][4], b[2][4], b2[2];
#pragma unroll
            for (int fi = 0; fi < 2; ++fi)
                ldsm4(a[fi], sb + arow + fi * 2048 + (((kc + hi16) ^ ax) << 4));
#pragma unroll
            for (int g = 0; g < 2; ++g)
                ldsm4(b[g], sb + brow + g * 2048 + (((kc + hi16) ^ ax) << 4));
            ldsm2(b2, sb + brow2 + (((kc + sel2) ^ ax) << 4));
#pragma unroll
            for (int fi = 0; fi < 2; ++fi) {
#pragma unroll
                for (int nf = 0; nf < 4; ++nf)
                    mma16816(acc[fi][nf], a[fi], b[nf >> 1][nf & 1], b[nf >> 1][(nf & 1) + 2]);
                mma16816(acc[fi][4], a[fi], b2[0], b2[1]);
            }
        }
    }
    __syncthreads();

#pragma unroll
    for (int fi = 0; fi < 2; ++fi)
#pragma unroll
        for (int j = 0; j < 5; ++j) {
            int n = wn * 40 + j * 8 + 2 * (l & 3);
            int mlo = m0 + wm * 32 + fi * 16 + (l >> 2);
            __nv_bfloat162 v0{__float2bfloat16(acc[fi][j][0]), __float2bfloat16(acc[fi][j][1])};
            __nv_bfloat162 v1{__float2bfloat16(acc[fi][j][2]), __float2bfloat16(acc[fi][j][3])};
            *(__nv_bfloat162*)(g_xa + (size_t)mlo * 80 + n) = v0;
            *(__nv_bfloat162*)(g_xa + (size_t)(mlo + 8) * 80 + n) = v1;
        }
}

// ------------------- main kernel --------------------------------------------
// 512 threads, tile M=256 x N=128; 16 warps = 4(m) x 4(n); warp 64x32.
// Phase 1: 16 int8 chunks (K=128 each; [q_xlo|q_xhi]·[q_whi|q_wlo], s32 acc).
// Phase 2: 16 bf16 chunks (K=64 each; xhi·Whi, f32 acc seeded from phase 1).
#define M_STG 49152

__device__ __forceinline__ void main_load(int c, uint32_t sb, int m0, int n0, int tid) {
    const char* xp = (c < 16) ? (const char*)g_xq : (const char*)g_xhi;
    const char* wp = (c < 16) ? (const char*)g_wq : (const char*)g_whi;
    size_t kb = (size_t)(c & 15) * 128;
#pragma unroll
    for (int i = 0; i < 6; ++i) {
        int id = tid + (i << 9);
        if (id < 2048) {
            int row = id >> 3, c16 = id & 7;
            CPA16(sb + row * 128 + ((c16 ^ (row & 7)) << 4),
                  xp + (size_t)(m0 + row) * 2048 + kb + c16 * 16);
        } else {
            int id2 = id - 2048;
            int row = id2 >> 3, c16 = id2 & 7;
            CPA16(sb + 32768 + row * 128 + ((c16 ^ (row & 7)) << 4),
                  wp + (size_t)(n0 + row) * 2048 + kb + c16 * 16);
        }
    }
}

__device__ __forceinline__ void corr_load(int br, uint32_t ep, int m0, int n0, int tid) {
    int row = tid >> 1, ch = tid & 1;
    uint32_t slot = (uint32_t)(((row & 3) * 2 + ch) ^ ((row >> 2) & 1));
    uint32_t off = (uint32_t)((row >> 2) * 128) + slot * 16;
    CPA16(ep + off, (const char*)(g_xa + (size_t)(m0 + row) * 80 + br * 16) + ch * 16);
    if (tid < 256)
        CPA16(ep + 8192 + off, (const char*)(g_bc + ((size_t)br * NN + n0 + row) * 16) + ch * 16);
}

__global__ void __launch_bounds__(512, 1) main_kernel(const float* __restrict__ bias,
                                                      float* __restrict__ out) {
    extern __shared__ char sm[];
    __shared__ float s_sx[256];
    __shared__ float s_sw[128];
    const uint32_t base = s2u(sm);
    const int tid = threadIdx.x, wid = tid >> 5, l = tid & 31;
    const int n0 = blockIdx.x * 128, m0 = blockIdx.y * 256;
    const int wm = wid & 3, wn = wid >> 2;

    if (tid < 256) s_sx[tid] = g_sx[m0 + tid];
    else if (tid < 384) s_sw[tid - 256] = g_sw[n0 + tid - 256];

    main_load(0, base, m0, n0, tid); CPCOMMIT();
    main_load(1, base + M_STG, m0, n0, tid); CPCOMMIT();

    const uint32_t arow = (uint32_t)((wm * 64 + (l & 15)) * 128);
    const uint32_t brow = (uint32_t)((wn * 32 + (l & 15)) * 128) + 32768;
    const uint32_t ax = (uint32_t)(l & 7);
    const uint32_t hi16 = (uint32_t)(l >> 4);

    float acc[4][4][4];
    {
        // -------- phase 1: int8 correction GEMM (K = 2048 int8) --------
        int S[4][4][4];
#pragma unroll
        for (int i = 0; i < 4; ++i)
#pragma unroll
            for (int j = 0; j < 4; ++j)
#pragma unroll
                for (int k = 0; k < 4; ++k) S[i][j][k] = 0;

        for (int c = 0; c < 16; ++c) {
            uint32_t sb = base + (c % 3) * M_STG;
            CPWAIT(1);
            __syncthreads();
            main_load(c + 2, base + ((c + 2) % 3) * M_STG, m0, n0, tid); CPCOMMIT();
#pragma unroll
            for (int ks = 0; ks < 4; ++ks) {
                uint32_t kc = (uint32_t)(ks * 2);
                uint32_t a[4][4], b[2][4];
#pragma unroll
                for (int fi = 0; fi < 4; ++fi)
                    ldsm4(a[fi], sb + arow + fi * 2048 + (((kc + hi16) ^ ax) << 4));
#pragma unroll
                for (int g = 0; g < 2; ++g)
                    ldsm4(b[g], sb + brow + g * 2048 + (((kc + hi16) ^ ax) << 4));
#pragma unroll
                for (int fi = 0; fi < 4; ++fi)
#pragma unroll
                    for (int nf = 0; nf < 4; ++nf)
                        imma16832(S[fi][nf], a[fi], b[nf >> 1][nf & 1], b[nf >> 1][(nf & 1) + 2]);
            }
        }

        // -------- convert s32 -> f32 with per-row scales --------
#pragma unroll
        for (int fi = 0; fi < 4; ++fi) {
            float sxa = s_sx[wm * 64 + fi * 16 + (l >> 2)];
            float sxb = s_sx[wm * 64 + fi * 16 + (l >> 2) + 8];
#pragma unroll
            for (int j = 0; j < 4; ++j) {
                float sw0 = s_sw[wn * 32 + j * 8 + 2 * (l & 3)];
                float sw1 = s_sw[wn * 32 + j * 8 + 2 * (l & 3) + 1];
                acc[fi][j][0] = (float)S[fi][j][0] * sxa * sw0;
                acc[fi][j][1] = (float)S[fi][j][1] * sxa * sw1;
                acc[fi][j][2] = (float)S[fi][j][2] * sxb * sw0;
                acc[fi][j][3] = (float)S[fi][j][3] * sxb * sw1;
            }
        }
    }

    // -------- phase 2: bf16 hi*hi GEMM (K = 1024) --------
    for (int c = 16; c < 32; ++c) {
        uint32_t sb = base + (c % 3) * M_STG;
        if (c == 31) { CPWAIT(0); } else { CPWAIT(1); }
        __syncthreads();
        if (c + 2 < 32) { main_load(c + 2, base + ((c + 2) % 3) * M_STG, m0, n0, tid); CPCOMMIT(); }
#pragma unroll
        for (int ks = 0; ks < 4; ++ks) {
            uint32_t kc = (uint32_t)(ks * 2);
            uint32_t a[4][4], b[2][4];
#pragma unroll
            for (int fi = 0; fi < 4; ++fi)
                ldsm4(a[fi], sb + arow + fi * 2048 + (((kc + hi16) ^ ax) << 4));
#pragma unroll
            for (int g = 0; g < 2; ++g)
                ldsm4(b[g], sb + brow + g * 2048 + (((kc + hi16) ^ ax) << 4));
#pragma unroll
            for (int fi = 0; fi < 4; ++fi)
#pragma unroll
                for (int nf = 0; nf < 4; ++nf)
                    mma16816(acc[fi][nf], a[fi], b[nf >> 1][nf & 1], b[nf >> 1][(nf & 1) + 2]);
        }
    }
    __syncthreads();

    // fold bias
#pragma unroll
    for (int j = 0; j < 4; ++j) {
        float2 bv = *(const float2*)(bias + n0 + wn * 32 + j * 8 + 2 * (l & 3));
#pragma unroll
        for (int fi = 0; fi < 4; ++fi) {
            acc[fi][j][0] += bv.x; acc[fi][j][1] += bv.y;
            acc[fi][j][2] += bv.x; acc[fi][j][3] += bv.y;
        }
    }

    // ---- per-branch rank-16 correction + store ----
    corr_load(0, base, m0, n0, tid); CPCOMMIT();
    corr_load(1, base + 16384, m0, n0, tid); CPCOMMIT();

    for (int br = 0; br < NBR; ++br) {
        uint32_t ep = base + (uint32_t)(br & 1) * 16384;
        if (br < 4) { CPWAIT(1); } else { CPWAIT(0); }
        __syncthreads();

        uint32_t b[2][4];
#pragma unroll
        for (int g = 0; g < 2; ++g) {
            int row = wn * 32 + g * 16 + (l & 15);
            uint32_t ad = ep + 8192 + (uint32_t)((row >> 2) * 128) +
                          (((uint32_t)((row & 3) * 2) + hi16) ^ (uint32_t)((row >> 2) & 1)) * 16;
            ldsm4(b[g], ad);
        }

        float* ob = out + (size_t)br * MM * NN;
#pragma unroll
        for (int h = 0; h < 2; ++h) {
            uint32_t a[2][4];
            float corr[2][4][4];
#pragma unroll
            for (int f2 = 0; f2 < 2; ++f2) {
                int fi = h * 2 + f2;
                int row = wm * 64 + fi * 16 + (l & 15);
                uint32_t ad = ep + (uint32_t)((row >> 2) * 128) +
                              (((uint32_t)((row & 3) * 2) + hi16) ^ (uint32_t)((row >> 2) & 1)) * 16;
                ldsm4(a[f2], ad);
            }
#pragma unroll
            for (int f2 = 0; f2 < 2; ++f2)
#pragma unroll
                for (int nf = 0; nf < 4; ++nf) {
#pragma unroll
                    for (int k = 0; k < 4; ++k) corr[f2][nf][k] = 0.f;
                    mma16816(corr[f2][nf], a[f2], b[nf >> 1][nf & 1], b[nf >> 1][(nf & 1) + 2]);
                }
#pragma unroll
            for (int f2 = 0; f2 < 2; ++f2) {
                int fi = h * 2 + f2;
                int mlo = m0 + wm * 64 + fi * 16 + (l >> 2);
#pragma unroll
                for (int j = 0; j < 4; ++j) {
                    int n = n0 + wn * 32 + j * 8 + 2 * (l & 3);
                    float2 v0{acc[fi][j][0] + corr[f2][j][0], acc[fi][j][1] + corr[f2][j][1]};
                    float2 v1{acc[fi][j][2] + corr[f2][j][2], acc[fi][j][3] + corr[f2][j][3]};
                    *(float2*)(ob + (size_t)mlo * NN + n) = v0;
                    *(float2*)(ob + (size_t)(mlo + 8) * NN + n) = v1;
                }
            }
        }
        __syncthreads();
        if (br + 2 < NBR) { corr_load(br + 2, ep, m0, n0, tid); CPCOMMIT(); }
    }
}

// ------------------- launcher -----------------------------------------------
extern "C" void kernel_launch(void* const* d_in, const int* in_sizes, int n_in,
                              void* d_out, int out_size)
{
    const float* x       = (const float*)d_in[0];
    const float* W       = (const float*)d_in[1];
    const float* b       = (const float*)d_in[2];
    const float* A_sh    = (const float*)d_in[3];
    const float* B_sh    = (const float*)d_in[4];
    const float* A_tasks = (const float*)d_in[5];
    const float* B_tasks = (const float*)d_in[6];
    const float* tscale  = (const float*)d_in[7];
    float* out           = (float*)d_out;

    static bool attr_done = false;
    if (!attr_done) {
        cudaFuncSetAttribute(main_kernel, cudaFuncAttributeMaxDynamicSharedMemorySize, 3 * M_STG);
        cudaFuncSetAttribute(xa_kernel,  cudaFuncAttributeMaxDynamicSharedMemorySize, 3 * XA_STG);
        attr_done = true;
    }

    quant_x_k<<<MM / 8, 256>>>(x);
    quant_w_k<<<NN / 8, 256>>>(W);
    conv_a_k<<<80, 256>>>(A_sh, A_tasks);
    prep_bc_k<<<20, 256>>>(B_sh, B_tasks, tscale);
    xa_kernel<<<MM / 128, 256, 3 * XA_STG>>>();
    main_kernel<<<dim3(NN / 128, MM / 256), 512, 3 * M_STG>>>(b, out);
}

// round 9
// speedup vs baseline: 1.5621x; 1.5621x over previous
#include <cuda_runtime.h>
#include <cuda_bf16.h>
#include <cstdint>

#define MM 32768
#define KK 1024
#define NN 1024
#define NBR 5

// ------------------- static device scratch ---------------------------------
__device__ __nv_bfloat16 g_xhi[(size_t)MM * KK];
__device__ __nv_bfloat16 g_xlo[(size_t)MM * KK];
__device__ __nv_bfloat16 g_whi[(size_t)NN * KK];
__device__ __nv_bfloat16 g_wlo[(size_t)NN * KK];
__device__ __nv_bfloat16 g_abf[80 * KK];                 // [80][1024] bf16
__device__ __nv_bfloat16 g_bc[(size_t)NBR * NN * 16];    // [br][n][16], scale folded
__device__ __nv_bfloat16 g_xa[(size_t)MM * 80];          // [m][80] bf16

// ------------------- helpers -----------------------------------------------
__device__ __forceinline__ uint32_t s2u(const void* p) {
    uint32_t a;
    asm("{ .reg .u64 t; cvta.to.shared.u64 t, %1; cvt.u32.u64 %0, t; }" : "=r"(a) : "l"(p));
    return a;
}
#define CPA16(d, s) asm volatile("cp.async.cg.shared.global [%0], [%1], 16;" :: "r"(d), "l"(s))
#define CPCOMMIT()  asm volatile("cp.async.commit_group;")
#define CPWAIT(n)   asm volatile("cp.async.wait_group %0;" :: "n"(n))

__device__ __forceinline__ void ldsm4(uint32_t* r, uint32_t a) {
    asm volatile("ldmatrix.sync.aligned.m8n8.x4.shared.b16 {%0,%1,%2,%3}, [%4];"
                 : "=r"(r[0]), "=r"(r[1]), "=r"(r[2]), "=r"(r[3]) : "r"(a));
}
__device__ __forceinline__ void ldsm2(uint32_t* r, uint32_t a) {
    asm volatile("ldmatrix.sync.aligned.m8n8.x2.shared.b16 {%0,%1}, [%2];"
                 : "=r"(r[0]), "=r"(r[1]) : "r"(a));
}
__device__ __forceinline__ void mma16816(float* c, const uint32_t* a, uint32_t b0, uint32_t b1) {
    asm volatile("mma.sync.aligned.m16n8k16.row.col.f32.bf16.bf16.f32 "
                 "{%0,%1,%2,%3},{%4,%5,%6,%7},{%8,%9},{%0,%1,%2,%3};"
                 : "+f"(c[0]), "+f"(c[1]), "+f"(c[2]), "+f"(c[3])
                 : "r"(a[0]), "r"(a[1]), "r"(a[2]), "r"(a[3]), "r"(b0), "r"(b1));
}
__device__ __forceinline__ void split2(float v, __nv_bfloat16& h, __nv_bfloat16& l) {
    h = __float2bfloat16(v);
    l = __float2bfloat16(v - __bfloat162float(h));
}

// ------------------- prep kernels ------------------------------------------
__global__ void __launch_bounds__(256) split_x_k(const float* __restrict__ x) {
    size_t i = ((size_t)blockIdx.x * 256 + threadIdx.x) * 4;
    float4 v = *(const float4*)(x + i);
    float f[4] = {v.x, v.y, v.z, v.w};
    __nv_bfloat162 h2[2], l2[2];
#pragma unroll
    for (int j = 0; j < 2; ++j) {
        __nv_bfloat16 h0, l0, h1, l1;
        split2(f[2 * j], h0, l0); split2(f[2 * j + 1], h1, l1);
        h2[j].x = h0; h2[j].y = h1; l2[j].x = l0; l2[j].y = l1;
    }
    ((__nv_bfloat162*)(g_xhi + i))[0] = h2[0]; ((__nv_bfloat162*)(g_xhi + i))[1] = h2[1];
    ((__nv_bfloat162*)(g_xlo + i))[0] = l2[0]; ((__nv_bfloat162*)(g_xlo + i))[1] = l2[1];
}
__global__ void __launch_bounds__(256) split_w_k(const float* __restrict__ w) {
    size_t i = ((size_t)blockIdx.x * 256 + threadIdx.x) * 4;
    float4 v = *(const float4*)(w + i);
    float f[4] = {v.x, v.y, v.z, v.w};
    __nv_bfloat162 h2[2], l2[2];
#pragma unroll
    for (int j = 0; j < 2; ++j) {
        __nv_bfloat16 h0, l0, h1, l1;
        split2(f[2 * j], h0, l0); split2(f[2 * j + 1], h1, l1);
        h2[j].x = h0; h2[j].y = h1; l2[j].x = l0; l2[j].y = l1;
    }
    ((__nv_bfloat162*)(g_whi + i))[0] = h2[0]; ((__nv_bfloat162*)(g_whi + i))[1] = h2[1];
    ((__nv_bfloat162*)(g_wlo + i))[0] = l2[0]; ((__nv_bfloat162*)(g_wlo + i))[1] = l2[1];
}
__global__ void __launch_bounds__(256) conv_a_k(const float* __restrict__ A_sh,
                                                const float* __restrict__ A_tasks) {
    size_t i = ((size_t)blockIdx.x * 256 + threadIdx.x) * 4;   // < 81920
    const float* src = (i < 16384) ? (A_sh + i) : (A_tasks + (i - 16384));
    float4 v = *(const float4*)src;
    __nv_bfloat162 a{__float2bfloat16(v.x), __float2bfloat16(v.y)};
    __nv_bfloat162 b{__float2bfloat16(v.z), __float2bfloat16(v.w)};
    ((__nv_bfloat162*)(g_abf + i))[0] = a; ((__nv_bfloat162*)(g_abf + i))[1] = b;
}
__global__ void __launch_bounds__(256) prep_bc_k(const float* __restrict__ B_sh,
                                                 const float* __restrict__ B_tasks,
                                                 const float* __restrict__ ts) {
    int id = blockIdx.x * 256 + threadIdx.x;   // < 5120
    int br = id >> 10, n = id & 1023;
    const float* row = (br == 0) ? (B_sh + (size_t)n * 16)
                                 : (B_tasks + ((size_t)(br - 1) * NN + n) * 16);
    float s = (br == 0) ? 1.0f : ts[br - 1];
    __nv_bfloat16* dst = g_bc + ((size_t)br * NN + n) * 16;
#pragma unroll
    for (int r = 0; r < 16; ++r) dst[r] = __float2bfloat16(s * row[r]);
}

// ------------------- XA kernel (HMMA, single bf16) --------------------------
#define XA_STG 26624

__device__ __forceinline__ void xa_load(int c, uint32_t sb, int m0, int tid) {
    int k0 = c << 6;
#pragma unroll
    for (int i = 0; i < 7; ++i) {
        int id = tid + (i << 8);
        if (id < 1024) {
            int row = id >> 3, c16 = id & 7;
            CPA16(sb + row * 128 + ((c16 ^ (row & 7)) << 4),
                  (const char*)(g_xhi + (size_t)(m0 + row) * KK + k0) + c16 * 16);
        } else if (id < 1664) {
            int id2 = id - 1024;
            int row = id2 >> 3, c16 = id2 & 7;
            CPA16(sb + 16384 + row * 128 + ((c16 ^ (row & 7)) << 4),
                  (const char*)(g_abf + (size_t)row * KK + k0) + c16 * 16);
        }
    }
}

__global__ void __launch_bounds__(256, 1) xa_kernel() {
    extern __shared__ char sm[];
    const uint32_t base = s2u(sm);
    const int tid = threadIdx.x, wid = tid >> 5, l = tid & 31;
    const int m0 = blockIdx.x * 128;
    const int wm = wid & 3, wn = wid >> 2;

    float acc[2][5][4];
#pragma unroll
    for (int i = 0; i < 2; ++i)
#pragma unroll
        for (int j = 0; j < 5; ++j)
#pragma unroll
            for (int k = 0; k < 4; ++k) acc[i][j][k] = 0.f;

    xa_load(0, base, m0, tid); CPCOMMIT();
    xa_load(1, base + XA_STG, m0, tid); CPCOMMIT();

    const uint32_t arow  = (uint32_t)((wm * 32 + (l & 15)) * 128);
    const uint32_t brow  = (uint32_t)((wn * 40 + (l & 15)) * 128) + 16384;
    const uint32_t brow2 = (uint32_t)((wn * 40 + 32 + (l & 7)) * 128) + 16384;
    const uint32_t ax = (uint32_t)(l & 7);
    const uint32_t hi16 = (uint32_t)(l >> 4);
    const uint32_t sel2 = (uint32_t)((l >> 3) & 1);

    for (int c = 0; c < 16; ++c) {
        uint32_t sb = base + (c % 3) * XA_STG;
        if (c == 15) { CPWAIT(0); } else { CPWAIT(1); }
        __syncthreads();
        if (c + 2 < 16) { xa_load(c + 2, base + ((c + 2) % 3) * XA_STG, m0, tid); CPCOMMIT(); }
#pragma unroll
        for (int ks = 0; ks < 4; ++ks) {
            uint32_t kc = (uint32_t)(ks * 2);
            uint32_t a[2][4], b[2][4], b2[2];
#pragma unroll
            for (int fi = 0; fi < 2; ++fi)
                ldsm4(a[fi], sb + arow + fi * 2048 + (((kc + hi16) ^ ax) << 4));
#pragma unroll
            for (int g = 0; g < 2; ++g)
                ldsm4(b[g], sb + brow + g * 2048 + (((kc + hi16) ^ ax) << 4));
            ldsm2(b2, sb + brow2 + (((kc + sel2) ^ ax) << 4));
#pragma unroll
            for (int fi = 0; fi < 2; ++fi) {
#pragma unroll
                for (int nf = 0; nf < 4; ++nf)
                    mma16816(acc[fi][nf], a[fi], b[nf >> 1][nf & 1], b[nf >> 1][(nf & 1) + 2]);
                mma16816(acc[fi][4], a[fi], b2[0], b2[1]);
            }
        }
    }
    __syncthreads();

#pragma unroll
    for (int fi = 0; fi < 2; ++fi)
#pragma unroll
        for (int j = 0; j < 5; ++j) {
            int n = wn * 40 + j * 8 + 2 * (l & 3);
            int mlo = m0 + wm * 32 + fi * 16 + (l >> 2);
            __nv_bfloat162 v0{__float2bfloat16(acc[fi][j][0]), __float2bfloat16(acc[fi][j][1])};
            __nv_bfloat162 v1{__float2bfloat16(acc[fi][j][2]), __float2bfloat16(acc[fi][j][3])};
            *(__nv_bfloat162*)(g_xa + (size_t)mlo * 80 + n) = v0;
            *(__nv_bfloat162*)(g_xa + (size_t)(mlo + 8) * 80 + n) = v1;
        }
}

// ------------------- main kernel --------------------------------------------
// 512 threads, tile M=256 x N=128; 16 warps = 4(m) x 4(n); warp 64x32.
// 16 k-groups (K=64 each).  Per group, stage {xhi, xlo, Whi, Wlo} ONCE (96KB),
// then run 3 term passes (hi*hi, lo*hi, hi*lo) out of the same buffers.
// Group layout: XH @0 (32KB) | XL @32768 (32KB) | WH @65536 (16KB) | WL @81920.
// 2 stages x 96KB = 192KB smem.
#define M_STG 98304

__device__ __forceinline__ void grp_load(int g, uint32_t sb, int m0, int n0, int tid) {
    size_t kb = (size_t)g * 128;   // byte offset of this K-slice within a row
#pragma unroll
    for (int i = 0; i < 12; ++i) {
        int id = tid + (i << 9);   // 0..6143
        if (id < 2048) {
            int row = id >> 3, c16 = id & 7;
            CPA16(sb + row * 128 + ((c16 ^ (row & 7)) << 4),
                  (const char*)(g_xhi + (size_t)(m0 + row) * KK) + kb + c16 * 16);
        } else if (id < 4096) {
            int id2 = id - 2048; int row = id2 >> 3, c16 = id2 & 7;
            CPA16(sb + 32768 + row * 128 + ((c16 ^ (row & 7)) << 4),
                  (const char*)(g_xlo + (size_t)(m0 + row) * KK) + kb + c16 * 16);
        } else if (id < 5120) {
            int id2 = id - 4096; int row = id2 >> 3, c16 = id2 & 7;
            CPA16(sb + 65536 + row * 128 + ((c16 ^ (row & 7)) << 4),
                  (const char*)(g_whi + (size_t)(n0 + row) * KK) + kb + c16 * 16);
        } else {
            int id2 = id - 5120; int row = id2 >> 3, c16 = id2 & 7;
            CPA16(sb + 81920 + row * 128 + ((c16 ^ (row & 7)) << 4),
                  (const char*)(g_wlo + (size_t)(n0 + row) * KK) + kb + c16 * 16);
        }
    }
}

__device__ __forceinline__ void corr_load(int br, uint32_t ep, int m0, int n0, int tid) {
    int row = tid >> 1, ch = tid & 1;
    uint32_t slot = (uint32_t)(((row & 3) * 2 + ch) ^ ((row >> 2) & 1));
    uint32_t off = (uint32_t)((row >> 2) * 128) + slot * 16;
    CPA16(ep + off, (const char*)(g_xa + (size_t)(m0 + row) * 80 + br * 16) + ch * 16);
    if (tid < 256)
        CPA16(ep + 8192 + off, (const char*)(g_bc + ((size_t)br * NN + n0 + row) * 16) + ch * 16);
}

__global__ void __launch_bounds__(512, 1) main_kernel(const float* __restrict__ bias,
                                                      float* __restrict__ out) {
    extern __shared__ char sm[];
    const uint32_t base = s2u(sm);
    const int tid = threadIdx.x, wid = tid >> 5, l = tid & 31;
    const int n0 = blockIdx.x * 128, m0 = blockIdx.y * 256;
    const int wm = wid & 3, wn = wid >> 2;

    float acc[4][4][4];
#pragma unroll
    for (int i = 0; i < 4; ++i)
#pragma unroll
        for (int j = 0; j < 4; ++j)
#pragma unroll
            for (int k = 0; k < 4; ++k) acc[i][j][k] = 0.f;

    grp_load(0, base, m0, n0, tid); CPCOMMIT();
    grp_load(1, base + M_STG, m0, n0, tid); CPCOMMIT();

    const uint32_t arow = (uint32_t)((wm * 64 + (l & 15)) * 128);
    const uint32_t brow = (uint32_t)((wn * 32 + (l & 15)) * 128);
    const uint32_t ax = (uint32_t)(l & 7);
    const uint32_t hi16 = (uint32_t)(l >> 4);

    for (int g = 0; g < 16; ++g) {
        uint32_t sb = base + (uint32_t)(g & 1) * M_STG;
        if (g == 15) { CPWAIT(0); } else { CPWAIT(1); }
        __syncthreads();
#pragma unroll
        for (int p = 0; p < 3; ++p) {
            const uint32_t aoff = (p == 1) ? 32768u : 0u;          // XL for pass 1
            const uint32_t boff = (p == 2) ? 81920u : 65536u;      // WL for pass 2
#pragma unroll
            for (int ks = 0; ks < 4; ++ks) {
                uint32_t kc = (uint32_t)(ks * 2);
                uint32_t a[4][4], b[2][4];
#pragma unroll
                for (int fi = 0; fi < 4; ++fi)
                    ldsm4(a[fi], sb + aoff + arow + fi * 2048 + (((kc + hi16) ^ ax) << 4));
#pragma unroll
                for (int gg = 0; gg < 2; ++gg)
                    ldsm4(b[gg], sb + boff + brow + gg * 2048 + (((kc + hi16) ^ ax) << 4));
#pragma unroll
                for (int fi = 0; fi < 4; ++fi)
#pragma unroll
                    for (int nf = 0; nf < 4; ++nf)
                        mma16816(acc[fi][nf], a[fi], b[nf >> 1][nf & 1], b[nf >> 1][(nf & 1) + 2]);
            }
        }
        __syncthreads();
        if (g + 2 < 16) { grp_load(g + 2, sb, m0, n0, tid); CPCOMMIT(); }
    }

    // fold bias
#pragma unroll
    for (int j = 0; j < 4; ++j) {
        float2 bv = *(const float2*)(bias + n0 + wn * 32 + j * 8 + 2 * (l & 3));
#pragma unroll
        for (int fi = 0; fi < 4; ++fi) {
            acc[fi][j][0] += bv.x; acc[fi][j][1] += bv.y;
            acc[fi][j][2] += bv.x; acc[fi][j][3] += bv.y;
        }
    }

    // ---- per-branch rank-16 correction + store (double-buffered staging) ----
    corr_load(0, base, m0, n0, tid); CPCOMMIT();
    corr_load(1, base + 16384, m0, n0, tid); CPCOMMIT();

    for (int br = 0; br < NBR; ++br) {
        uint32_t ep = base + (uint32_t)(br & 1) * 16384;
        if (br < 4) { CPWAIT(1); } else { CPWAIT(0); }
        __syncthreads();

        uint32_t b[2][4];
#pragma unroll
        for (int g = 0; g < 2; ++g) {
            int row = wn * 32 + g * 16 + (l & 15);
            uint32_t ad = ep + 8192 + (uint32_t)((row >> 2) * 128) +
                          (((uint32_t)((row & 3) * 2) + hi16) ^ (uint32_t)((row >> 2) & 1)) * 16;
            ldsm4(b[g], ad);
        }

        float* ob = out + (size_t)br * MM * NN;
#pragma unroll
        for (int h = 0; h < 2; ++h) {
            uint32_t a[2][4];
            float corr[2][4][4];
#pragma unroll
            for (int f2 = 0; f2 < 2; ++f2) {
                int fi = h * 2 + f2;
                int row = wm * 64 + fi * 16 + (l & 15);
                uint32_t ad = ep + (uint32_t)((row >> 2) * 128) +
                              (((uint32_t)((row & 3) * 2) + hi16) ^ (uint32_t)((row >> 2) & 1)) * 16;
                ldsm4(a[f2], ad);
            }
#pragma unroll
            for (int f2 = 0; f2 < 2; ++f2)
#pragma unroll
                for (int nf = 0; nf < 4; ++nf) {
#pragma unroll
                    for (int k = 0; k < 4; ++k) corr[f2][nf][k] = 0.f;
                    mma16816(corr[f2][nf], a[f2], b[nf >> 1][nf & 1], b[nf >> 1][(nf & 1) + 2]);
                }
#pragma unroll
            for (int f2 = 0; f2 < 2; ++f2) {
                int fi = h * 2 + f2;
                int mlo = m0 + wm * 64 + fi * 16 + (l >> 2);
#pragma unroll
                for (int j = 0; j < 4; ++j) {
                    int n = n0 + wn * 32 + j * 8 + 2 * (l & 3);
                    float2 v0{acc[fi][j][0] + corr[f2][j][0], acc[fi][j][1] + corr[f2][j][1]};
                    float2 v1{acc[fi][j][2] + corr[f2][j][2], acc[fi][j][3] + corr[f2][j][3]};
                    *(float2*)(ob + (size_t)mlo * NN + n) = v0;
                    *(float2*)(ob + (size_t)(mlo + 8) * NN + n) = v1;
                }
            }
        }
        __syncthreads();
        if (br + 2 < NBR) { corr_load(br + 2, ep, m0, n0, tid); CPCOMMIT(); }
    }
}

// ------------------- launcher -----------------------------------------------
extern "C" void kernel_launch(void* const* d_in, const int* in_sizes, int n_in,
                              void* d_out, int out_size)
{
    const float* x       = (const float*)d_in[0];
    const float* W       = (const float*)d_in[1];
    const float* b       = (const float*)d_in[2];
    const float* A_sh    = (const float*)d_in[3];
    const float* B_sh    = (const float*)d_in[4];
    const float* A_tasks = (const float*)d_in[5];
    const float* B_tasks = (const float*)d_in[6];
    const float* tscale  = (const float*)d_in[7];
    float* out           = (float*)d_out;

    static bool attr_done = false;
    if (!attr_done) {
        cudaFuncSetAttribute(main_kernel, cudaFuncAttributeMaxDynamicSharedMemorySize, 2 * M_STG);
        cudaFuncSetAttribute(xa_kernel,  cudaFuncAttributeMaxDynamicSharedMemorySize, 3 * XA_STG);
        attr_done = true;
    }

    split_x_k<<<MM * KK / 1024, 256>>>(x);
    split_w_k<<<NN * KK / 1024, 256>>>(W);
    conv_a_k<<<80, 256>>>(A_sh, A_tasks);
    prep_bc_k<<<20, 256>>>(B_sh, B_tasks, tscale);
    xa_kernel<<<MM / 128, 256, 3 * XA_STG>>>();
    main_kernel<<<dim3(NN / 128, MM / 256), 512, 2 * M_STG>>>(b, out);
}